// round 16
// baseline (speedup 1.0000x reference)
#include <cuda_runtime.h>
#include <math.h>

#define NSP   589824   // 64*96*96
#define BATCH 2
#define TOPK  2048
#define CAND  2048     // count(prefix > P) < 2048 by construction
#define STASH 16384
#define SSTA  2048     // smem-resident stash window
#define ANCH  12.0f
#define NBIN  4096     // 12-bit prefix bins

// ---------------- device scratch (zero-initialized at load; re-zeroed each
// replay by k_iou's cleanup tail so the graph is replay-stable) -------------
__device__ __align__(16) unsigned g_histA[BATCH][NBIN];
__device__ unsigned g_arrive[BATCH];
__device__ unsigned g_cnt[BATCH];
__device__ unsigned g_scnt[BATCH];
__device__ __align__(16) unsigned long long g_cand[BATCH][CAND];
__device__ __align__(16) unsigned long long g_stash[BATCH][STASH];
__device__ float    g_sc[BATCH][TOPK];
__device__ float    g_bx[BATCH][TOPK][6];
__device__ __align__(16) float g_pb[BATCH][TOPK][8];  // lo0,lo1,lo2,hi0 | hi1,hi2,vol,0
__device__ __align__(16) unsigned long long g_mask[BATCH][TOPK][32]; // junk masked in k_nms

__device__ __forceinline__ unsigned fkey(float f) {
    unsigned u = __float_as_uint(f);
    return (u & 0x80000000u) ? ~u : (u | 0x80000000u);
}
__device__ __forceinline__ float fromkey(unsigned k) {
    unsigned u = (k & 0x80000000u) ? (k ^ 0x80000000u) : ~k;
    return __uint_as_float(u);
}

// ---------------- K1: fused hist + spin-barrier + select + collect ---------
__global__ void __launch_bounds__(256) k_topk(const float* __restrict__ scores) {
    __shared__ unsigned h[NBIN];
    __shared__ unsigned sh_P;
    __shared__ unsigned wt[8], wa[8];
    int b = blockIdx.y, t = threadIdx.x;
#pragma unroll
    for (int i = t; i < NBIN; i += 256) h[i] = 0u;
    __syncthreads();
    const float4* p = (const float4*)(scores + (long)b * NSP) + blockIdx.x * 1024;
    float4 v0 = p[t], v1 = p[256 + t], v2 = p[512 + t], v3 = p[768 + t];
    unsigned key[16];
    {
        float vv[16] = { v0.x,v0.y,v0.z,v0.w, v1.x,v1.y,v1.z,v1.w,
                         v2.x,v2.y,v2.z,v2.w, v3.x,v3.y,v3.z,v3.w };
#pragma unroll
        for (int q = 0; q < 16; q++) {
            key[q] = fkey(vv[q]);
            atomicAdd(&h[key[q] >> 20], 1u);
        }
    }
    __syncthreads();
#pragma unroll
    for (int i = t; i < NBIN; i += 256) {
        unsigned c = h[i];
        if (c) atomicAdd(&g_histA[b][i], c);
    }
    __threadfence();
    __syncthreads();
    if (t == 0) {
        atomicAdd(&g_arrive[b], 1u);
        while (((volatile unsigned*)g_arrive)[b] < 144u) __nanosleep(64);
    }
    __syncthreads();
    int lane = t & 31, wid = t >> 5;
    const uint4* h4 = (const uint4*)g_histA[b] + t * 4;
    uint4 hv4[4];
    unsigned local = 0;
#pragma unroll
    for (int j = 0; j < 4; j++) {
        hv4[j] = __ldcg(h4 + j);
        local += hv4[j].x + hv4[j].y + hv4[j].z + hv4[j].w;
    }
    unsigned suf = local;
#pragma unroll
    for (int off = 1; off < 32; off <<= 1) {
        unsigned x = __shfl_down_sync(0xffffffffu, suf, off);
        if (lane + off < 32) suf += x;
    }
    if (lane == 0) wt[wid] = suf;
    __syncthreads();
    if (wid == 0 && lane < 8) {
        unsigned w = wt[lane], ws = w;
#pragma unroll
        for (int off = 1; off < 8; off <<= 1) {
            unsigned x = __shfl_down_sync(0xffu, ws, off);
            if (lane + off < 8) ws += x;
        }
        wa[lane] = ws - w;
    }
    __syncthreads();
    unsigned T = wa[wid] + (suf - local);
    if (T < TOPK && T + local >= TOPK) {
        unsigned acc = T, P = 0;
        int found = 0;
#pragma unroll
        for (int j = 3; j >= 0; j--) {
            unsigned hh[4] = { hv4[j].w, hv4[j].z, hv4[j].y, hv4[j].x };
#pragma unroll
            for (int q = 0; q < 4; q++) {
                if (!found) {
                    if (acc + hh[q] >= TOPK) { P = (unsigned)(t*16 + 4*j + (3-q)); found = 1; }
                    else acc += hh[q];
                }
            }
        }
        sh_P = P;
    }
    __syncthreads();
    unsigned pref = sh_P;
#pragma unroll
    for (int q = 0; q < 16; q++) {
        unsigned k = key[q];
        unsigned pp = k >> 20;
        if (pp >= pref) {
            unsigned idx = (unsigned)((blockIdx.x * 1024 + (q >> 2) * 256 + t) * 4 + (q & 3));
            unsigned long long pk = ((unsigned long long)k << 32) | (unsigned)(~idx);
            if (pp > pref) {
                unsigned pos = atomicAdd(&g_cnt[b], 1u);
                if (pos < CAND) g_cand[b][pos] = pk;
            } else {
                unsigned sq = atomicAdd(&g_scnt[b], 1u);
                if (sq < STASH) g_stash[b][sq] = pk;
            }
        }
    }
}

// ---------------- K2: rank + staged parallel gather ------------------------
__device__ __forceinline__ void emit_box(int b, unsigned long long mine, unsigned rank,
                                         const float* __restrict__ bboxes) {
    if (rank >= TOPK) return;
    int i = (int)rank;
    unsigned key = (unsigned)(mine >> 32);
    unsigned idx = ~(unsigned)(mine & 0xFFFFFFFFull);
    g_sc[b][i] = fromkey(key);
    int z = idx / 9216, r = idx % 9216, y = r / 96, x = r % 96;
    long base = (long)b * 6 * NSP + idx;
    float czyx[3] = { (float)z + 0.5f, (float)y + 0.5f, (float)x + 0.5f };
    float c3[3], s3[3];
#pragma unroll
    for (int c = 0; c < 3; c++) {
        c3[c] = bboxes[base + (long)c * NSP] * ANCH + czyx[c];
        g_bx[b][i][c] = c3[c];
    }
#pragma unroll
    for (int c = 0; c < 3; c++) {
        s3[c] = expf(bboxes[base + (long)(c + 3) * NSP]) * ANCH;
        g_bx[b][i][c + 3] = s3[c];
    }
    float4 L = make_float4(c3[0] - 0.5f * s3[0], c3[1] - 0.5f * s3[1],
                           c3[2] - 0.5f * s3[2], c3[0] + 0.5f * s3[0]);
    float4 H = make_float4(c3[1] + 0.5f * s3[1], c3[2] + 0.5f * s3[2],
                           s3[0] * s3[1] * s3[2], 0.0f);
    ((float4*)g_pb[b][i])[0] = L;
    ((float4*)g_pb[b][i])[1] = H;
}

__global__ void __launch_bounds__(256) k_rankgather(const float* __restrict__ bboxes) {
    int b = blockIdx.y, bx = blockIdx.x;
    int t = threadIdx.x, lane = t & 31, w = t >> 5;
    unsigned cnt  = g_cnt[b];  if (cnt  > CAND)  cnt  = CAND;
    unsigned scnt = g_scnt[b]; if (scnt > STASH) scnt = STASH;

    if (bx < 64) {
        __shared__ unsigned long long sc[CAND];
        __shared__ unsigned long long st_mine[40];
        __shared__ unsigned st_rank[40];
        __shared__ int st_n;
        if (t == 0) st_n = 0;
#pragma unroll
        for (int m = 0; m < 8; m++) {
            unsigned j = (unsigned)(m * 256 + t);
            sc[j] = (j < cnt) ? g_cand[b][j] : 0ull;
        }
        __syncthreads();
#pragma unroll
        for (int s = 0; s < 4; s++) {
            unsigned slot = (unsigned)(bx * 32 + s * 8 + w);
            if (slot < cnt) {
                unsigned long long mine = sc[slot];
                unsigned c = 0;
#pragma unroll
                for (int j = lane; j < CAND; j += 32) c += (sc[j] > mine) ? 1u : 0u;
                unsigned rank = __reduce_add_sync(0xffffffffu, c);
                if (lane == 0 && rank < TOPK) {
                    int p = atomicAdd(&st_n, 1);
                    st_mine[p] = mine; st_rank[p] = rank;
                }
            }
        }
        __syncthreads();
        int n = st_n;
        if (t < n) emit_box(b, st_mine[t], st_rank[t], bboxes);
    } else {
        __shared__ unsigned long long sst[SSTA];
        __shared__ unsigned long long sm_mine[8][128];
        __shared__ unsigned sm_rank[8][128];
        const unsigned long long* st = g_stash[b];
        unsigned ns = scnt < SSTA ? scnt : SSTA;
        for (unsigned j = (unsigned)t; j < ns; j += 256) sst[j] = st[j];
        __syncthreads();
        int w_n = 0;
        for (unsigned slot = (bx - 64) * 8 + (unsigned)w; slot < scnt; slot += 128) {
            unsigned long long mine = st[slot];
            unsigned c0 = 0, c1 = 0, c2 = 0, c3 = 0;
            unsigned j = lane;
            for (; j + 96 < ns; j += 128) {
                c0 += (sst[j]      > mine) ? 1u : 0u;
                c1 += (sst[j + 32] > mine) ? 1u : 0u;
                c2 += (sst[j + 64] > mine) ? 1u : 0u;
                c3 += (sst[j + 96] > mine) ? 1u : 0u;
            }
            for (; j < ns; j += 32) c0 += (sst[j] > mine) ? 1u : 0u;
            for (j = SSTA + lane; j < scnt; j += 32)
                c0 += (st[j] > mine) ? 1u : 0u;
            unsigned rank = cnt + __reduce_add_sync(0xffffffffu, c0 + c1 + c2 + c3);
            if (rank < TOPK) {
                if (lane == 0) { sm_mine[w][w_n] = mine; sm_rank[w][w_n] = rank; }
                w_n++;
            }
        }
        __syncwarp();
        for (int e = lane; e < w_n; e += 32)
            emit_box(b, sm_mine[w][e], sm_rank[w][e], bboxes);
    }
}

// ---------------- K3: IoU bitmask + replay-state cleanup -------------------
__global__ void __launch_bounds__(128) k_iou() {
    int b = blockIdx.z, rbk = blockIdx.y, cb = blockIdx.x, t = threadIdx.x;
    {
        unsigned flat = ((blockIdx.z * gridDim.y + blockIdx.y) * gridDim.x + blockIdx.x) * 128u + t;
        if (flat < BATCH * NBIN / 2) ((unsigned long long*)g_histA)[flat] = 0ull;
        if (flat < BATCH) { g_cnt[flat] = 0u; g_scnt[flat] = 0u; g_arrive[flat] = 0u; }
    }
    int row0 = rbk << 8;
    int c0 = cb << 6;
    if (c0 + 63 <= row0) return;
    __shared__ float4 scol[64][2];
    { int j = t >> 1, h = t & 1; scol[j][h] = ((const float4*)g_pb[b][c0 + j])[h]; }
    __syncthreads();
    int r1 = row0 + t, r2 = row0 + 128 + t;
    float4 aL = ((const float4*)g_pb[b][r1])[0];
    float4 aH = ((const float4*)g_pb[b][r1])[1];
    float4 bL = ((const float4*)g_pb[b][r2])[0];
    float4 bH = ((const float4*)g_pb[b][r2])[1];
    unsigned a0 = 0u, a1 = 0u, b0 = 0u, b1 = 0u;
#pragma unroll
    for (int j = 0; j < 64; j++) {
        float4 cL = scol[j][0], cH = scol[j][1];
        float e0 = fmaxf(fminf(aL.w, cL.w) - fmaxf(aL.x, cL.x), 0.0f);
        float e1 = fmaxf(fminf(aH.x, cH.x) - fmaxf(aL.y, cL.y), 0.0f);
        float e2 = fmaxf(fminf(aH.y, cH.y) - fmaxf(aL.z, cL.z), 0.0f);
        float inter1 = e0 * e1 * e2;
        bool p1 = (5.0f * inter1 > aH.z + cH.z);
        float f0 = fmaxf(fminf(bL.w, cL.w) - fmaxf(bL.x, cL.x), 0.0f);
        float f1 = fmaxf(fminf(bH.x, cH.x) - fmaxf(bL.y, cL.y), 0.0f);
        float f2 = fmaxf(fminf(bH.y, cH.y) - fmaxf(bL.z, cL.z), 0.0f);
        float inter2 = f0 * f1 * f2;
        bool p2 = (5.0f * inter2 > bH.z + cH.z);
        unsigned bb = 1u << (j & 31);
        if (j < 32) { if (p1) a0 |= bb; if (p2) b0 |= bb; }
        else        { if (p1) a1 |= bb; if (p2) b1 |= bb; }
    }
    unsigned long long bits1 = (unsigned long long)a0 | ((unsigned long long)a1 << 32);
    unsigned long long bits2 = (unsigned long long)b0 | ((unsigned long long)b1 << 32);
    if (c0 + 63 > r1) {
        if (r1 >= c0) { int k = r1 - c0; bits1 &= (~0ull) << (k + 1); }
        g_mask[b][r1][cb] = bits1;
    }
    if (c0 + 63 > r2) {
        if (r2 >= c0) { int k = r2 - c0; bits2 &= (~0ull) << (k + 1); }
        g_mask[b][r2][cb] = bits2;
    }
}

// ---------------- K4: greedy NMS — alive-row ffs skip chain ----------------
// Block 1024: warp 0 = chain (ffs over alive rows only), warps 1-31 loaders.
__global__ void __launch_bounds__(1024) k_nms(float* __restrict__ out) {
    int b = blockIdx.x, tid = threadIdx.x;
    __shared__ unsigned long long s_rows[2][64][32];
    __shared__ unsigned long long s_remv[32];
    unsigned long long remv = 0ull;

    if (tid >= 32) {                                   // preload chunk 0
        for (int k = tid - 32; k < 2048; k += 992) {
            s_rows[0][k >> 5][k & 31] = g_mask[b][k >> 5][k & 31];
        }
    }
    __syncthreads();

    for (int c = 0; c < 32; c++) {                     // 32 chunks of 64 rows
        int cur = c & 1;
        if (tid >= 32 && c < 31) {                     // prefetch next chunk
            int nb = cur ^ 1;
            for (int k = tid - 32; k < 2048; k += 992) {
                s_rows[nb][k >> 5][k & 31] = g_mask[b][((c + 1) << 6) + (k >> 5)][k & 31];
            }
        }
        if (tid < 32) {
            unsigned long long rmask = (tid < c) ? 0ull : ~0ull;  // junk lanes
            unsigned long long notloc = ~__shfl_sync(0xffffffffu, remv, c);
            while (notloc) {                           // warp-uniform loop
                int rr = __ffsll((long long)notloc) - 1;
                unsigned long long d    = s_rows[cur][rr][c];    // broadcast
                unsigned long long rdat = s_rows[cur][rr][tid] & rmask;
                if (rr == 63) { d = 0ull; if (tid == c) rdat = 0ull; }
                remv |= rdat;                          // off-chain, lane-parallel
                notloc &= ~(d | (1ull << rr));         // chain: ffs->LDS->LOP
            }
        }
        __syncthreads();
    }
    if (tid < 32) s_remv[tid] = remv;
    __syncthreads();

#pragma unroll
    for (int m = 0; m < 2; m++) {
        int i = m * 1024 + tid;
        bool keep = !((s_remv[i >> 6] >> (i & 63)) & 1ull);
        float* o = out + ((long)b * TOPK + i) * 7;
        o[0] = keep ? g_sc[b][i] : 0.0f;
#pragma unroll
        for (int c = 0; c < 6; c++) o[1 + c] = keep ? g_bx[b][i][c] : 0.0f;
    }
}

// ---------------- launch ---------------------------------------------------
extern "C" void kernel_launch(void* const* d_in, const int* in_sizes, int n_in,
                              void* d_out, int out_size) {
    const float* bboxes = (const float*)d_in[0];   // (2,6,64,96,96)
    const float* scores = (const float*)d_in[1];   // (2,64,96,96)
    float* out = (float*)d_out;                    // (2,2048,7)

    k_topk<<<dim3(144, BATCH), 256>>>(scores);     // hist+select+collect fused
    k_rankgather<<<dim3(80, BATCH), 256>>>(bboxes);
    k_iou<<<dim3(32, 8, BATCH), 128>>>();
    k_nms<<<BATCH, 1024>>>(out);
}

// round 17
// speedup vs baseline: 2.1655x; 2.1655x over previous
#include <cuda_runtime.h>
#include <math.h>

#define NSP   589824   // 64*96*96
#define BATCH 2
#define TOPK  2048
#define CAND  2048     // count(prefix > P) < 2048 by construction
#define STASH 16384
#define SSTA  2048     // smem-resident stash window
#define ANCH  12.0f
#define NBIN  4096     // 12-bit prefix bins

// ---------------- device scratch (zero-initialized at load; re-zeroed each
// replay by k_iou's cleanup tail so the graph is replay-stable) -------------
__device__ __align__(16) unsigned g_histA[BATCH][NBIN];
__device__ unsigned g_arrive[BATCH];
__device__ unsigned g_cnt[BATCH];
__device__ unsigned g_scnt[BATCH];
__device__ __align__(16) unsigned long long g_cand[BATCH][CAND];
__device__ __align__(16) unsigned long long g_stash[BATCH][STASH];
__device__ float    g_sc[BATCH][TOPK];
__device__ float    g_bx[BATCH][TOPK][6];
__device__ __align__(16) float g_pb[BATCH][TOPK][8];  // lo0,lo1,lo2,hi0 | hi1,hi2,vol,0
__device__ __align__(16) unsigned long long g_mask[BATCH][TOPK][32]; // junk masked in k_nms

__device__ __forceinline__ unsigned fkey(float f) {
    unsigned u = __float_as_uint(f);
    return (u & 0x80000000u) ? ~u : (u | 0x80000000u);
}
__device__ __forceinline__ float fromkey(unsigned k) {
    unsigned u = (k & 0x80000000u) ? (k ^ 0x80000000u) : ~k;
    return __uint_as_float(u);
}

// ---------------- K1: fused hist + spin-barrier + select + collect ---------
__global__ void __launch_bounds__(256) k_topk(const float* __restrict__ scores) {
    __shared__ unsigned h[NBIN];
    __shared__ unsigned sh_P;
    __shared__ unsigned wt[8], wa[8];
    int b = blockIdx.y, t = threadIdx.x;
#pragma unroll
    for (int i = t; i < NBIN; i += 256) h[i] = 0u;
    __syncthreads();
    const float4* p = (const float4*)(scores + (long)b * NSP) + blockIdx.x * 1024;
    float4 v0 = p[t], v1 = p[256 + t], v2 = p[512 + t], v3 = p[768 + t];
    unsigned key[16];
    {
        float vv[16] = { v0.x,v0.y,v0.z,v0.w, v1.x,v1.y,v1.z,v1.w,
                         v2.x,v2.y,v2.z,v2.w, v3.x,v3.y,v3.z,v3.w };
#pragma unroll
        for (int q = 0; q < 16; q++) {
            key[q] = fkey(vv[q]);
            atomicAdd(&h[key[q] >> 20], 1u);
        }
    }
    __syncthreads();
#pragma unroll
    for (int i = t; i < NBIN; i += 256) {
        unsigned c = h[i];
        if (c) atomicAdd(&g_histA[b][i], c);
    }
    __threadfence();
    __syncthreads();
    if (t == 0) {
        atomicAdd(&g_arrive[b], 1u);
        while (((volatile unsigned*)g_arrive)[b] < 144u) __nanosleep(64);
    }
    __syncthreads();
    int lane = t & 31, wid = t >> 5;
    const uint4* h4 = (const uint4*)g_histA[b] + t * 4;
    uint4 hv4[4];
    unsigned local = 0;
#pragma unroll
    for (int j = 0; j < 4; j++) {
        hv4[j] = __ldcg(h4 + j);
        local += hv4[j].x + hv4[j].y + hv4[j].z + hv4[j].w;
    }
    unsigned suf = local;
#pragma unroll
    for (int off = 1; off < 32; off <<= 1) {
        unsigned x = __shfl_down_sync(0xffffffffu, suf, off);
        if (lane + off < 32) suf += x;
    }
    if (lane == 0) wt[wid] = suf;
    __syncthreads();
    if (wid == 0 && lane < 8) {
        unsigned w = wt[lane], ws = w;
#pragma unroll
        for (int off = 1; off < 8; off <<= 1) {
            unsigned x = __shfl_down_sync(0xffu, ws, off);
            if (lane + off < 8) ws += x;
        }
        wa[lane] = ws - w;
    }
    __syncthreads();
    unsigned T = wa[wid] + (suf - local);
    if (T < TOPK && T + local >= TOPK) {
        unsigned acc = T, P = 0;
        int found = 0;
#pragma unroll
        for (int j = 3; j >= 0; j--) {
            unsigned hh[4] = { hv4[j].w, hv4[j].z, hv4[j].y, hv4[j].x };
#pragma unroll
            for (int q = 0; q < 4; q++) {
                if (!found) {
                    if (acc + hh[q] >= TOPK) { P = (unsigned)(t*16 + 4*j + (3-q)); found = 1; }
                    else acc += hh[q];
                }
            }
        }
        sh_P = P;
    }
    __syncthreads();
    unsigned pref = sh_P;
#pragma unroll
    for (int q = 0; q < 16; q++) {
        unsigned k = key[q];
        unsigned pp = k >> 20;
        if (pp >= pref) {
            unsigned idx = (unsigned)((blockIdx.x * 1024 + (q >> 2) * 256 + t) * 4 + (q & 3));
            unsigned long long pk = ((unsigned long long)k << 32) | (unsigned)(~idx);
            if (pp > pref) {
                unsigned pos = atomicAdd(&g_cnt[b], 1u);
                if (pos < CAND) g_cand[b][pos] = pk;
            } else {
                unsigned sq = atomicAdd(&g_scnt[b], 1u);
                if (sq < STASH) g_stash[b][sq] = pk;
            }
        }
    }
}

// ---------------- K2: rank + staged parallel gather ------------------------
__device__ __forceinline__ void emit_box(int b, unsigned long long mine, unsigned rank,
                                         const float* __restrict__ bboxes) {
    if (rank >= TOPK) return;
    int i = (int)rank;
    unsigned key = (unsigned)(mine >> 32);
    unsigned idx = ~(unsigned)(mine & 0xFFFFFFFFull);
    g_sc[b][i] = fromkey(key);
    int z = idx / 9216, r = idx % 9216, y = r / 96, x = r % 96;
    long base = (long)b * 6 * NSP + idx;
    float czyx[3] = { (float)z + 0.5f, (float)y + 0.5f, (float)x + 0.5f };
    float c3[3], s3[3];
#pragma unroll
    for (int c = 0; c < 3; c++) {
        c3[c] = bboxes[base + (long)c * NSP] * ANCH + czyx[c];
        g_bx[b][i][c] = c3[c];
    }
#pragma unroll
    for (int c = 0; c < 3; c++) {
        s3[c] = expf(bboxes[base + (long)(c + 3) * NSP]) * ANCH;
        g_bx[b][i][c + 3] = s3[c];
    }
    float4 L = make_float4(c3[0] - 0.5f * s3[0], c3[1] - 0.5f * s3[1],
                           c3[2] - 0.5f * s3[2], c3[0] + 0.5f * s3[0]);
    float4 H = make_float4(c3[1] + 0.5f * s3[1], c3[2] + 0.5f * s3[2],
                           s3[0] * s3[1] * s3[2], 0.0f);
    ((float4*)g_pb[b][i])[0] = L;
    ((float4*)g_pb[b][i])[1] = H;
}

__global__ void __launch_bounds__(256) k_rankgather(const float* __restrict__ bboxes) {
    int b = blockIdx.y, bx = blockIdx.x;
    int t = threadIdx.x, lane = t & 31, w = t >> 5;
    unsigned cnt  = g_cnt[b];  if (cnt  > CAND)  cnt  = CAND;
    unsigned scnt = g_scnt[b]; if (scnt > STASH) scnt = STASH;

    if (bx < 64) {
        __shared__ unsigned long long sc[CAND];
        __shared__ unsigned long long st_mine[40];
        __shared__ unsigned st_rank[40];
        __shared__ int st_n;
        if (t == 0) st_n = 0;
#pragma unroll
        for (int m = 0; m < 8; m++) {
            unsigned j = (unsigned)(m * 256 + t);
            sc[j] = (j < cnt) ? g_cand[b][j] : 0ull;
        }
        __syncthreads();
#pragma unroll
        for (int s = 0; s < 4; s++) {
            unsigned slot = (unsigned)(bx * 32 + s * 8 + w);
            if (slot < cnt) {
                unsigned long long mine = sc[slot];
                unsigned c = 0;
#pragma unroll
                for (int j = lane; j < CAND; j += 32) c += (sc[j] > mine) ? 1u : 0u;
                unsigned rank = __reduce_add_sync(0xffffffffu, c);
                if (lane == 0 && rank < TOPK) {
                    int p = atomicAdd(&st_n, 1);
                    st_mine[p] = mine; st_rank[p] = rank;
                }
            }
        }
        __syncthreads();
        int n = st_n;
        if (t < n) emit_box(b, st_mine[t], st_rank[t], bboxes);
    } else {
        __shared__ unsigned long long sst[SSTA];
        __shared__ unsigned long long sm_mine[8][128];
        __shared__ unsigned sm_rank[8][128];
        const unsigned long long* st = g_stash[b];
        unsigned ns = scnt < SSTA ? scnt : SSTA;
        for (unsigned j = (unsigned)t; j < ns; j += 256) sst[j] = st[j];
        __syncthreads();
        int w_n = 0;
        for (unsigned slot = (bx - 64) * 8 + (unsigned)w; slot < scnt; slot += 128) {
            unsigned long long mine = st[slot];
            unsigned c0 = 0, c1 = 0, c2 = 0, c3 = 0;
            unsigned j = lane;
            for (; j + 96 < ns; j += 128) {
                c0 += (sst[j]      > mine) ? 1u : 0u;
                c1 += (sst[j + 32] > mine) ? 1u : 0u;
                c2 += (sst[j + 64] > mine) ? 1u : 0u;
                c3 += (sst[j + 96] > mine) ? 1u : 0u;
            }
            for (; j < ns; j += 32) c0 += (sst[j] > mine) ? 1u : 0u;
            for (j = SSTA + lane; j < scnt; j += 32)
                c0 += (st[j] > mine) ? 1u : 0u;
            unsigned rank = cnt + __reduce_add_sync(0xffffffffu, c0 + c1 + c2 + c3);
            if (rank < TOPK) {
                if (lane == 0) { sm_mine[w][w_n] = mine; sm_rank[w][w_n] = rank; }
                w_n++;
            }
        }
        __syncwarp();
        for (int e = lane; e < w_n; e += 32)
            emit_box(b, sm_mine[w][e], sm_rank[w][e], bboxes);
    }
}

// ---------------- K3: IoU bitmask + replay-state cleanup -------------------
__global__ void __launch_bounds__(128) k_iou() {
    int b = blockIdx.z, rbk = blockIdx.y, cb = blockIdx.x, t = threadIdx.x;
    {
        unsigned flat = ((blockIdx.z * gridDim.y + blockIdx.y) * gridDim.x + blockIdx.x) * 128u + t;
        if (flat < BATCH * NBIN / 2) ((unsigned long long*)g_histA)[flat] = 0ull;
        if (flat < BATCH) { g_cnt[flat] = 0u; g_scnt[flat] = 0u; g_arrive[flat] = 0u; }
    }
    int row0 = rbk << 8;
    int c0 = cb << 6;
    if (c0 + 63 <= row0) return;
    __shared__ float4 scol[64][2];
    { int j = t >> 1, h = t & 1; scol[j][h] = ((const float4*)g_pb[b][c0 + j])[h]; }
    __syncthreads();
    int r1 = row0 + t, r2 = row0 + 128 + t;
    float4 aL = ((const float4*)g_pb[b][r1])[0];
    float4 aH = ((const float4*)g_pb[b][r1])[1];
    float4 bL = ((const float4*)g_pb[b][r2])[0];
    float4 bH = ((const float4*)g_pb[b][r2])[1];
    unsigned a0 = 0u, a1 = 0u, b0 = 0u, b1 = 0u;
#pragma unroll
    for (int j = 0; j < 64; j++) {
        float4 cL = scol[j][0], cH = scol[j][1];
        float e0 = fmaxf(fminf(aL.w, cL.w) - fmaxf(aL.x, cL.x), 0.0f);
        float e1 = fmaxf(fminf(aH.x, cH.x) - fmaxf(aL.y, cL.y), 0.0f);
        float e2 = fmaxf(fminf(aH.y, cH.y) - fmaxf(aL.z, cL.z), 0.0f);
        float inter1 = e0 * e1 * e2;
        bool p1 = (5.0f * inter1 > aH.z + cH.z);
        float f0 = fmaxf(fminf(bL.w, cL.w) - fmaxf(bL.x, cL.x), 0.0f);
        float f1 = fmaxf(fminf(bH.x, cH.x) - fmaxf(bL.y, cL.y), 0.0f);
        float f2 = fmaxf(fminf(bH.y, cH.y) - fmaxf(bL.z, cL.z), 0.0f);
        float inter2 = f0 * f1 * f2;
        bool p2 = (5.0f * inter2 > bH.z + cH.z);
        unsigned bb = 1u << (j & 31);
        if (j < 32) { if (p1) a0 |= bb; if (p2) b0 |= bb; }
        else        { if (p1) a1 |= bb; if (p2) b1 |= bb; }
    }
    unsigned long long bits1 = (unsigned long long)a0 | ((unsigned long long)a1 << 32);
    unsigned long long bits2 = (unsigned long long)b0 | ((unsigned long long)b1 << 32);
    if (c0 + 63 > r1) {
        if (r1 >= c0) { int k = r1 - c0; bits1 &= (~0ull) << (k + 1); }
        g_mask[b][r1][cb] = bits1;
    }
    if (c0 + 63 > r2) {
        if (r2 >= c0) { int k = r2 - c0; bits2 &= (~0ull) << (k + 1); }
        g_mask[b][r2][cb] = bits2;
    }
}

// ---------------- K4: greedy NMS — speculative sparse fast path ------------
// Per chunk: if no seed-alive row has a nonzero diagonal word, the chunk's
// masks are fully determined by the seed word -> branch-free pipelined OR.
// Otherwise fall back to the exact serial chain (R13).
__global__ void __launch_bounds__(1024) k_nms(float* __restrict__ out) {
    int b = blockIdx.x, tid = threadIdx.x;
    __shared__ unsigned long long s_rows[2][64][32];
    __shared__ unsigned long long s_remv[32];
    unsigned long long remv = 0ull;

    if (tid >= 32) {                                   // preload chunk 0
        for (int k = tid - 32; k < 2048; k += 992) {
            s_rows[0][k >> 5][k & 31] = g_mask[b][k >> 5][k & 31];
        }
    }
    __syncthreads();

    for (int c = 0; c < 32; c++) {                     // 32 chunks of 64 rows
        int cur = c & 1;
        if (tid >= 32 && c < 31) {                     // prefetch next chunk
            int nb = cur ^ 1;
            for (int k = tid - 32; k < 2048; k += 992) {
                s_rows[nb][k >> 5][k & 31] = g_mask[b][((c + 1) << 6) + (k >> 5)][k & 31];
            }
        }
        if (tid < 32) {
            unsigned long long seed = __shfl_sync(0xffffffffu, remv, c);
            // check: any seed-alive row with a nonzero diag word?
            int r0 = 2 * tid, r1 = 2 * tid + 1;
            unsigned long long d0 = s_rows[cur][r0][c];
            unsigned long long d1 = (r1 == 63) ? 0ull : s_rows[cur][r1][c];
            if ((seed >> r0) & 1ull) d0 = 0ull;
            if ((seed >> r1) & 1ull) d1 = 0ull;
            bool needchain = __any_sync(0xffffffffu, (d0 | d1) != 0ull);
            if (!needchain) {
                // fast path: masks = seed for the whole chunk; pipelined OR
                unsigned long long acc = 0ull;
#pragma unroll
                for (int rr = 0; rr < 64; rr++) {
                    unsigned long long rdat = s_rows[cur][rr][tid];
                    if (rr == 63 && tid == c) rdat = 0ull;        // junk word
                    unsigned long long m =
                        (unsigned long long)((long long)(seed << (63 - rr)) >> 63);
                    acc |= rdat & ~m;
                }
                if (tid >= c) remv |= acc;             // lanes < c hold junk
            } else {
                // exact serial chain (rare)
                unsigned long long local = seed;
#pragma unroll
                for (int rr = 0; rr < 64; rr++) {
                    int i = (c << 6) + rr;
                    unsigned long long rdat = s_rows[cur][rr][tid];
                    unsigned long long rloc = s_rows[cur][rr][c];
                    if (64 * tid + 63 <= i) rdat = 0ull;
                    unsigned long long m =
                        (unsigned long long)((long long)(local << (63 - rr)) >> 63);
                    remv |= rdat & ~m;
                    local |= rloc & ~m;
                }
            }
        }
        __syncthreads();
    }
    if (tid < 32) s_remv[tid] = remv;
    __syncthreads();

#pragma unroll
    for (int m = 0; m < 2; m++) {
        int i = m * 1024 + tid;
        bool keep = !((s_remv[i >> 6] >> (i & 63)) & 1ull);
        float* o = out + ((long)b * TOPK + i) * 7;
        o[0] = keep ? g_sc[b][i] : 0.0f;
#pragma unroll
        for (int c = 0; c < 6; c++) o[1 + c] = keep ? g_bx[b][i][c] : 0.0f;
    }
}

// ---------------- launch ---------------------------------------------------
extern "C" void kernel_launch(void* const* d_in, const int* in_sizes, int n_in,
                              void* d_out, int out_size) {
    const float* bboxes = (const float*)d_in[0];   // (2,6,64,96,96)
    const float* scores = (const float*)d_in[1];   // (2,64,96,96)
    float* out = (float*)d_out;                    // (2,2048,7)

    k_topk<<<dim3(144, BATCH), 256>>>(scores);     // hist+select+collect fused
    k_rankgather<<<dim3(80, BATCH), 256>>>(bboxes);
    k_iou<<<dim3(32, 8, BATCH), 128>>>();
    k_nms<<<BATCH, 1024>>>(out);
}